// round 2
// baseline (speedup 1.0000x reference)
#include <cuda_runtime.h>
#include <cuda_bf16.h>
#include <cstdint>

// Problem constants
#define BATCH 4
#define SEQ   2048
#define EMB   1024          // E == D
#define NHEAD 16
#define HDIM  64
#define MROWS (BATCH * SEQ) // 8192

// ---------------- scratch (static device globals; no allocation) ------------
__device__ float g_qp[MROWS * EMB];
__device__ float g_kp[MROWS * EMB];
__device__ float g_vp[MROWS * EMB];
__device__ float g_att[MROWS * EMB];

// ---------------- SGEMM: C[M,Nc] = A[M,K] @ W[K,Nc] + bias --------------
// M=8192, K=1024, Nc=1024.  BM=128, BN=128, BK=8, TM=TN=8, 256 threads.
#define BM 128
#define BN 128
#define BK 8
#define TM 8
#define TN 8

__global__ __launch_bounds__(256, 2)
void sgemm_bias_kernel(const float* __restrict__ A,
                       const float* __restrict__ W,
                       const float* __restrict__ bias,
                       float* __restrict__ C)
{
    const int K  = EMB;
    const int Nc = EMB;

    __shared__ float As[BK][BM];
    __shared__ float Bs[BK][BN];

    const int tid = threadIdx.x;
    const int bx  = blockIdx.x;   // N tile
    const int by  = blockIdx.y;   // M tile

    const float* Aptr = A + (size_t)by * BM * K;
    const float* Wptr = W + (size_t)bx * BN;

    // A-tile load mapping: 128 rows x 8 cols = 1024 floats, float4 per thread
    const int aRow = tid >> 1;          // 0..127
    const int aCol = (tid & 1) * 4;     // 0 or 4
    // B-tile load mapping: 8 rows x 128 cols
    const int bRow = tid >> 5;          // 0..7
    const int bCol = (tid & 31) * 4;    // 0..124

    const int ty = tid >> 4;            // 0..15
    const int tx = tid & 15;            // 0..15

    float acc[TM][TN];
#pragma unroll
    for (int i = 0; i < TM; i++)
#pragma unroll
        for (int j = 0; j < TN; j++) acc[i][j] = 0.0f;

    for (int k0 = 0; k0 < K; k0 += BK) {
        float4 a4 = *(const float4*)(Aptr + (size_t)aRow * K + k0 + aCol);
        As[aCol + 0][aRow] = a4.x;
        As[aCol + 1][aRow] = a4.y;
        As[aCol + 2][aRow] = a4.z;
        As[aCol + 3][aRow] = a4.w;

        float4 b4 = *(const float4*)(Wptr + (size_t)(k0 + bRow) * Nc + bCol);
        *(float4*)&Bs[bRow][bCol] = b4;

        __syncthreads();

#pragma unroll
        for (int k = 0; k < BK; k++) {
            float4 a0 = *(const float4*)&As[k][ty * TM];
            float4 a1 = *(const float4*)&As[k][ty * TM + 4];
            float4 b0 = *(const float4*)&Bs[k][tx * TN];
            float4 b1 = *(const float4*)&Bs[k][tx * TN + 4];
            float rm[TM] = {a0.x, a0.y, a0.z, a0.w, a1.x, a1.y, a1.z, a1.w};
            float rn[TN] = {b0.x, b0.y, b0.z, b0.w, b1.x, b1.y, b1.z, b1.w};
#pragma unroll
            for (int i = 0; i < TM; i++)
#pragma unroll
                for (int j = 0; j < TN; j++)
                    acc[i][j] = fmaf(rm[i], rn[j], acc[i][j]);
        }
        __syncthreads();
    }

    // epilogue with bias
#pragma unroll
    for (int i = 0; i < TM; i++) {
        const int row = by * BM + ty * TM + i;
#pragma unroll
        for (int j = 0; j < TN; j += 4) {
            const int col = bx * BN + tx * TN + j;
            float4 o;
            o.x = acc[i][j + 0] + bias[col + 0];
            o.y = acc[i][j + 1] + bias[col + 1];
            o.z = acc[i][j + 2] + bias[col + 2];
            o.w = acc[i][j + 3] + bias[col + 3];
            *(float4*)(C + (size_t)row * Nc + col) = o;
        }
    }
}

// ---------------- Flash attention (fp32) ------------------------------------
// Grid: (SEQ/BQ, BATCH*NHEAD). 256 threads as 16x16; each thread owns a
// 4x4 tile of S (BQ x BKV) and a 4x4 tile of O (BQ x HDIM).
#define BQ  64
#define BKV 64
#define FPAD 68   // row stride (floats), multiple of 4 for float4 alignment

#define SM_QS 0
#define SM_KS (BQ * FPAD)
#define SM_VS (2 * BQ * FPAD)
#define SM_PS (3 * BQ * FPAD)
#define SMEM_FLOATS (4 * BQ * FPAD)
#define SMEM_BYTES  (SMEM_FLOATS * 4)

__global__ __launch_bounds__(256, 2)
void flash_attn_kernel(const float* __restrict__ qp,
                       const float* __restrict__ kp,
                       const float* __restrict__ vp,
                       float* __restrict__ out)
{
    extern __shared__ float sm[];
    float (*Qs)[FPAD] = (float (*)[FPAD])(sm + SM_QS);
    float (*Ks)[FPAD] = (float (*)[FPAD])(sm + SM_KS);
    float (*Vs)[FPAD] = (float (*)[FPAD])(sm + SM_VS);
    float (*Ps)[FPAD] = (float (*)[FPAD])(sm + SM_PS);

    const int tid = threadIdx.x;
    const int tx  = tid & 15;   // KV-col group / O-col group
    const int ty  = tid >> 4;   // Q-row group

    const int bh = blockIdx.y;
    const int b  = bh / NHEAD;
    const int h  = bh % NHEAD;
    const int q0 = blockIdx.x * BQ;

    const float scale = 0.125f; // 1/sqrt(64)

    const float* qbase = qp + ((size_t)b * SEQ) * EMB + h * HDIM;
    const float* kbase = kp + ((size_t)b * SEQ) * EMB + h * HDIM;
    const float* vbase = vp + ((size_t)b * SEQ) * EMB + h * HDIM;

    // Load Q tile: 64 rows x 64 floats = 1024 float4
    for (int i = tid; i < BQ * (HDIM / 4); i += 256) {
        const int row = i >> 4;
        const int c4  = (i & 15) * 4;
        float4 v4 = *(const float4*)(qbase + (size_t)(q0 + row) * EMB + c4);
        *(float4*)&Qs[row][c4] = v4;
    }

    float m_i[4], l_i[4], O[4][4];
#pragma unroll
    for (int i = 0; i < 4; i++) {
        m_i[i] = -1e30f;
        l_i[i] = 0.0f;
#pragma unroll
        for (int j = 0; j < 4; j++) O[i][j] = 0.0f;
    }
    __syncthreads();

    for (int t0 = 0; t0 < SEQ; t0 += BKV) {
        // load K,V tiles
        for (int i = tid; i < BKV * (HDIM / 4); i += 256) {
            const int row = i >> 4;
            const int c4  = (i & 15) * 4;
            *(float4*)&Ks[row][c4] =
                *(const float4*)(kbase + (size_t)(t0 + row) * EMB + c4);
            *(float4*)&Vs[row][c4] =
                *(const float4*)(vbase + (size_t)(t0 + row) * EMB + c4);
        }
        __syncthreads();

        // S = Q K^T (4x4 per thread)
        float s[4][4];
#pragma unroll
        for (int i = 0; i < 4; i++)
#pragma unroll
            for (int j = 0; j < 4; j++) s[i][j] = 0.0f;

#pragma unroll
        for (int d = 0; d < HDIM; d += 4) {
            float4 q4[4], k4[4];
#pragma unroll
            for (int i = 0; i < 4; i++) q4[i] = *(const float4*)&Qs[4 * ty + i][d];
#pragma unroll
            for (int j = 0; j < 4; j++) k4[j] = *(const float4*)&Ks[4 * tx + j][d];
#pragma unroll
            for (int i = 0; i < 4; i++)
#pragma unroll
                for (int j = 0; j < 4; j++) {
                    s[i][j] = fmaf(q4[i].x, k4[j].x, s[i][j]);
                    s[i][j] = fmaf(q4[i].y, k4[j].y, s[i][j]);
                    s[i][j] = fmaf(q4[i].z, k4[j].z, s[i][j]);
                    s[i][j] = fmaf(q4[i].w, k4[j].w, s[i][j]);
                }
        }

        // online softmax per row; reduce across tx (16 lanes within warp half)
#pragma unroll
        for (int i = 0; i < 4; i++) {
            float mx = -1e30f;
#pragma unroll
            for (int j = 0; j < 4; j++) {
                s[i][j] *= scale;
                mx = fmaxf(mx, s[i][j]);
            }
#pragma unroll
            for (int off = 1; off < 16; off <<= 1)
                mx = fmaxf(mx, __shfl_xor_sync(0xffffffffu, mx, off));

            const float mnew = fmaxf(m_i[i], mx);
            const float corr = __expf(m_i[i] - mnew);
            float rs = 0.0f;
#pragma unroll
            for (int j = 0; j < 4; j++) {
                const float p = __expf(s[i][j] - mnew);
                Ps[4 * ty + i][4 * tx + j] = p;
                rs += p;
            }
#pragma unroll
            for (int off = 1; off < 16; off <<= 1)
                rs += __shfl_xor_sync(0xffffffffu, rs, off);

            l_i[i] = l_i[i] * corr + rs;
            m_i[i] = mnew;
#pragma unroll
            for (int j = 0; j < 4; j++) O[i][j] *= corr;
        }
        __syncthreads(); // Ps complete

        // O += P @ V
#pragma unroll 4
        for (int kk = 0; kk < BKV; kk += 4) {
            float4 p4[4];
#pragma unroll
            for (int i = 0; i < 4; i++) p4[i] = *(const float4*)&Ps[4 * ty + i][kk];
            float4 v4[4];
#pragma unroll
            for (int t = 0; t < 4; t++) v4[t] = *(const float4*)&Vs[kk + t][4 * tx];
#pragma unroll
            for (int i = 0; i < 4; i++) {
                O[i][0] = fmaf(p4[i].x, v4[0].x, O[i][0]);
                O[i][1] = fmaf(p4[i].x, v4[0].y, O[i][1]);
                O[i][2] = fmaf(p4[i].x, v4[0].z, O[i][2]);
                O[i][3] = fmaf(p4[i].x, v4[0].w, O[i][3]);
                O[i][0] = fmaf(p4[i].y, v4[1].x, O[i][0]);
                O[i][1] = fmaf(p4[i].y, v4[1].y, O[i][1]);
                O[i][2] = fmaf(p4[i].y, v4[1].z, O[i][2]);
                O[i][3] = fmaf(p4[i].y, v4[1].w, O[i][3]);
                O[i][0] = fmaf(p4[i].z, v4[2].x, O[i][0]);
                O[i][1] = fmaf(p4[i].z, v4[2].y, O[i][1]);
                O[i][2] = fmaf(p4[i].z, v4[2].z, O[i][2]);
                O[i][3] = fmaf(p4[i].z, v4[2].w, O[i][3]);
                O[i][0] = fmaf(p4[i].w, v4[3].x, O[i][0]);
                O[i][1] = fmaf(p4[i].w, v4[3].y, O[i][1]);
                O[i][2] = fmaf(p4[i].w, v4[3].z, O[i][2]);
                O[i][3] = fmaf(p4[i].w, v4[3].w, O[i][3]);
            }
        }
        __syncthreads(); // done with Ks/Vs/Ps before next tile overwrites
    }

    // epilogue: normalize and write to g_att in [b,n, h*HD+d] layout
#pragma unroll
    for (int i = 0; i < 4; i++) {
        const float inv = 1.0f / l_i[i];
        const int row = q0 + 4 * ty + i;
        float4 o4;
        o4.x = O[i][0] * inv;
        o4.y = O[i][1] * inv;
        o4.z = O[i][2] * inv;
        o4.w = O[i][3] * inv;
        *(float4*)(out + ((size_t)b * SEQ + row) * EMB + h * HDIM + 4 * tx) = o4;
    }
}

// ---------------- launcher ---------------------------------------------------
extern "C" void kernel_launch(void* const* d_in, const int* in_sizes, int n_in,
                              void* d_out, int out_size)
{
    const float* q  = (const float*)d_in[0];
    const float* k  = (const float*)d_in[1];
    const float* v  = (const float*)d_in[2];
    const float* Wq = (const float*)d_in[3];
    const float* bq = (const float*)d_in[4];
    const float* Wk = (const float*)d_in[5];
    const float* bk = (const float*)d_in[6];
    const float* Wv = (const float*)d_in[7];
    const float* bv = (const float*)d_in[8];
    const float* Wo = (const float*)d_in[9];
    const float* bo = (const float*)d_in[10];
    float* out = (float*)d_out;

    float *qp, *kp, *vp, *att;
    cudaGetSymbolAddress((void**)&qp,  g_qp);
    cudaGetSymbolAddress((void**)&kp,  g_kp);
    cudaGetSymbolAddress((void**)&vp,  g_vp);
    cudaGetSymbolAddress((void**)&att, g_att);

    cudaFuncSetAttribute(flash_attn_kernel,
                         cudaFuncAttributeMaxDynamicSharedMemorySize, SMEM_BYTES);

    dim3 gemm_grid(EMB / BN, MROWS / BM);  // (8, 64)
    sgemm_bias_kernel<<<gemm_grid, 256>>>(q, Wq, bq, qp);
    sgemm_bias_kernel<<<gemm_grid, 256>>>(k, Wk, bk, kp);
    sgemm_bias_kernel<<<gemm_grid, 256>>>(v, Wv, bv, vp);

    dim3 attn_grid(SEQ / BQ, BATCH * NHEAD); // (32, 64)
    flash_attn_kernel<<<attn_grid, 256, SMEM_BYTES>>>(qp, kp, vp, att);

    sgemm_bias_kernel<<<gemm_grid, 256>>>(att, Wo, bo, out);
}

// round 3
// speedup vs baseline: 1.0638x; 1.0638x over previous
#include <cuda_runtime.h>
#include <cuda_bf16.h>
#include <cstdint>

// Problem constants
#define BATCH 4
#define SEQ   2048
#define EMB   1024          // E == D
#define NHEAD 16
#define HDIM  64
#define MROWS (BATCH * SEQ) // 8192

// ---------------- scratch (static device globals; no allocation) ------------
__device__ float g_qp[MROWS * EMB];
__device__ float g_kp[MROWS * EMB];
__device__ float g_vp[MROWS * EMB];
__device__ float g_att[MROWS * EMB];

// ============================================================================
// Tensor-core GEMM: C[M,N] = A[M,K] @ W[K,N] + bias, fp32 I/O.
// bf16x3 split: a = ah + al, b = bh + bl; a*b ~= ah*bh + ah*bl + al*bh.
// BM=128, BN=128, BK=32, 8 warps (2x4), warp tile 64x32, mma m16n8k16.
// ============================================================================
#define GBM 128
#define GBN 128
#define GBK 32
#define KPAD 40   // smem row stride in bf16 (conflict-free: 20 banks)

__device__ __forceinline__ void mma_bf16(float& d0, float& d1, float& d2, float& d3,
                                         uint32_t a0, uint32_t a1, uint32_t a2, uint32_t a3,
                                         uint32_t b0, uint32_t b1)
{
    asm volatile(
        "mma.sync.aligned.m16n8k16.row.col.f32.bf16.bf16.f32 "
        "{%0,%1,%2,%3}, {%4,%5,%6,%7}, {%8,%9}, {%0,%1,%2,%3};\n"
        : "+f"(d0), "+f"(d1), "+f"(d2), "+f"(d3)
        : "r"(a0), "r"(a1), "r"(a2), "r"(a3), "r"(b0), "r"(b1));
}

__device__ __forceinline__ void split_bf16(float a, __nv_bfloat16& hi, __nv_bfloat16& lo)
{
    hi = __float2bfloat16(a);
    lo = __float2bfloat16(a - __bfloat162float(hi));
}

__global__ __launch_bounds__(256)
void gemm_bf16x3_kernel(const float* __restrict__ A,
                        const float* __restrict__ W,
                        const float* __restrict__ bias,
                        float* __restrict__ C)
{
    const int K  = EMB;
    const int Nc = EMB;

    __shared__ __nv_bfloat16 Ash[GBM][KPAD];
    __shared__ __nv_bfloat16 Asl[GBM][KPAD];
    __shared__ __nv_bfloat16 Bsh[GBN][KPAD];   // [n][k] layout
    __shared__ __nv_bfloat16 Bsl[GBN][KPAD];

    const int tid  = threadIdx.x;
    const int warp = tid >> 5;
    const int lane = tid & 31;
    const int bx   = blockIdx.x;   // N tile
    const int by   = blockIdx.y;   // M tile

    const int wm = warp >> 2;      // 0..1  (m offset wm*64)
    const int wn = warp & 3;       // 0..3  (n offset wn*32)
    const int grp = lane >> 2;     // 0..7
    const int kp  = lane & 3;      // 0..3

    const float* Aptr = A + (size_t)by * GBM * K;

    // A load mapping: row = tid/2, 16 consecutive k per thread
    const int aRow  = tid >> 1;
    const int aKoff = (tid & 1) * 16;
    // B load mapping: k row = tid/8, 16 consecutive n per thread
    const int bK    = tid >> 3;
    const int bNoff = (tid & 7) * 16;

    float acc[4][4][4];
#pragma unroll
    for (int i = 0; i < 4; i++)
#pragma unroll
        for (int j = 0; j < 4; j++)
#pragma unroll
            for (int c = 0; c < 4; c++) acc[i][j][c] = 0.0f;

    for (int k0 = 0; k0 < K; k0 += GBK) {
        // ---- load & split A tile ----
#pragma unroll
        for (int i = 0; i < 4; i++) {
            float4 a4 = *(const float4*)(Aptr + (size_t)aRow * K + k0 + aKoff + 4 * i);
            __nv_bfloat16 h, l;
            split_bf16(a4.x, h, l); Ash[aRow][aKoff + 4*i + 0] = h; Asl[aRow][aKoff + 4*i + 0] = l;
            split_bf16(a4.y, h, l); Ash[aRow][aKoff + 4*i + 1] = h; Asl[aRow][aKoff + 4*i + 1] = l;
            split_bf16(a4.z, h, l); Ash[aRow][aKoff + 4*i + 2] = h; Asl[aRow][aKoff + 4*i + 2] = l;
            split_bf16(a4.w, h, l); Ash[aRow][aKoff + 4*i + 3] = h; Asl[aRow][aKoff + 4*i + 3] = l;
        }
        // ---- load & split B tile (transpose to [n][k]) ----
#pragma unroll
        for (int i = 0; i < 4; i++) {
            float4 b4 = *(const float4*)(W + (size_t)(k0 + bK) * Nc + bx * GBN + bNoff + 4 * i);
            __nv_bfloat16 h, l;
            split_bf16(b4.x, h, l); Bsh[bNoff + 4*i + 0][bK] = h; Bsl[bNoff + 4*i + 0][bK] = l;
            split_bf16(b4.y, h, l); Bsh[bNoff + 4*i + 1][bK] = h; Bsl[bNoff + 4*i + 1][bK] = l;
            split_bf16(b4.z, h, l); Bsh[bNoff + 4*i + 2][bK] = h; Bsl[bNoff + 4*i + 2][bK] = l;
            split_bf16(b4.w, h, l); Bsh[bNoff + 4*i + 3][bK] = h; Bsl[bNoff + 4*i + 3][bK] = l;
        }
        __syncthreads();

        // ---- compute: 2 k-steps of 16 ----
#pragma unroll
        for (int ks = 0; ks < GBK; ks += 16) {
            // B fragments for all 4 n-tiles (hi & lo)
            uint32_t bh[4][2], bl[4][2];
#pragma unroll
            for (int ni = 0; ni < 4; ni++) {
                const int n = wn * 32 + ni * 8 + grp;
                bh[ni][0] = *(const uint32_t*)&Bsh[n][ks + kp * 2];
                bh[ni][1] = *(const uint32_t*)&Bsh[n][ks + kp * 2 + 8];
                bl[ni][0] = *(const uint32_t*)&Bsl[n][ks + kp * 2];
                bl[ni][1] = *(const uint32_t*)&Bsl[n][ks + kp * 2 + 8];
            }
#pragma unroll
            for (int mi = 0; mi < 4; mi++) {
                const int r = wm * 64 + mi * 16 + grp;
                uint32_t ah0 = *(const uint32_t*)&Ash[r    ][ks + kp * 2];
                uint32_t ah1 = *(const uint32_t*)&Ash[r + 8][ks + kp * 2];
                uint32_t ah2 = *(const uint32_t*)&Ash[r    ][ks + kp * 2 + 8];
                uint32_t ah3 = *(const uint32_t*)&Ash[r + 8][ks + kp * 2 + 8];
                uint32_t al0 = *(const uint32_t*)&Asl[r    ][ks + kp * 2];
                uint32_t al1 = *(const uint32_t*)&Asl[r + 8][ks + kp * 2];
                uint32_t al2 = *(const uint32_t*)&Asl[r    ][ks + kp * 2 + 8];
                uint32_t al3 = *(const uint32_t*)&Asl[r + 8][ks + kp * 2 + 8];
#pragma unroll
                for (int ni = 0; ni < 4; ni++) {
                    float* d = acc[mi][ni];
                    mma_bf16(d[0], d[1], d[2], d[3], ah0, ah1, ah2, ah3, bh[ni][0], bh[ni][1]);
                    mma_bf16(d[0], d[1], d[2], d[3], ah0, ah1, ah2, ah3, bl[ni][0], bl[ni][1]);
                    mma_bf16(d[0], d[1], d[2], d[3], al0, al1, al2, al3, bh[ni][0], bh[ni][1]);
                }
            }
        }
        __syncthreads();
    }

    // ---- epilogue with bias ----
#pragma unroll
    for (int mi = 0; mi < 4; mi++) {
        const int r = by * GBM + wm * 64 + mi * 16 + grp;
#pragma unroll
        for (int ni = 0; ni < 4; ni++) {
            const int c = bx * GBN + wn * 32 + ni * 8 + kp * 2;
            const float b0 = bias[c], b1 = bias[c + 1];
            float2 o0 = make_float2(acc[mi][ni][0] + b0, acc[mi][ni][1] + b1);
            float2 o1 = make_float2(acc[mi][ni][2] + b0, acc[mi][ni][3] + b1);
            *(float2*)(C + (size_t)r * Nc + c)       = o0;
            *(float2*)(C + (size_t)(r + 8) * Nc + c) = o1;
        }
    }
}

// ---------------- Flash attention (fp32, unchanged from R2 baseline) --------
#define BQ  64
#define BKV 64
#define FPAD 68

#define SM_QS 0
#define SM_KS (BQ * FPAD)
#define SM_VS (2 * BQ * FPAD)
#define SM_PS (3 * BQ * FPAD)
#define SMEM_FLOATS (4 * BQ * FPAD)
#define SMEM_BYTES  (SMEM_FLOATS * 4)

__global__ __launch_bounds__(256, 2)
void flash_attn_kernel(const float* __restrict__ qp,
                       const float* __restrict__ kp,
                       const float* __restrict__ vp,
                       float* __restrict__ out)
{
    extern __shared__ float sm[];
    float (*Qs)[FPAD] = (float (*)[FPAD])(sm + SM_QS);
    float (*Ks)[FPAD] = (float (*)[FPAD])(sm + SM_KS);
    float (*Vs)[FPAD] = (float (*)[FPAD])(sm + SM_VS);
    float (*Ps)[FPAD] = (float (*)[FPAD])(sm + SM_PS);

    const int tid = threadIdx.x;
    const int tx  = tid & 15;
    const int ty  = tid >> 4;

    const int bh = blockIdx.y;
    const int b  = bh / NHEAD;
    const int h  = bh % NHEAD;
    const int q0 = blockIdx.x * BQ;

    const float scale = 0.125f;

    const float* qbase = qp + ((size_t)b * SEQ) * EMB + h * HDIM;
    const float* kbase = kp + ((size_t)b * SEQ) * EMB + h * HDIM;
    const float* vbase = vp + ((size_t)b * SEQ) * EMB + h * HDIM;

    for (int i = tid; i < BQ * (HDIM / 4); i += 256) {
        const int row = i >> 4;
        const int c4  = (i & 15) * 4;
        float4 v4 = *(const float4*)(qbase + (size_t)(q0 + row) * EMB + c4);
        *(float4*)&Qs[row][c4] = v4;
    }

    float m_i[4], l_i[4], O[4][4];
#pragma unroll
    for (int i = 0; i < 4; i++) {
        m_i[i] = -1e30f;
        l_i[i] = 0.0f;
#pragma unroll
        for (int j = 0; j < 4; j++) O[i][j] = 0.0f;
    }
    __syncthreads();

    for (int t0 = 0; t0 < SEQ; t0 += BKV) {
        for (int i = tid; i < BKV * (HDIM / 4); i += 256) {
            const int row = i >> 4;
            const int c4  = (i & 15) * 4;
            *(float4*)&Ks[row][c4] =
                *(const float4*)(kbase + (size_t)(t0 + row) * EMB + c4);
            *(float4*)&Vs[row][c4] =
                *(const float4*)(vbase + (size_t)(t0 + row) * EMB + c4);
        }
        __syncthreads();

        float s[4][4];
#pragma unroll
        for (int i = 0; i < 4; i++)
#pragma unroll
            for (int j = 0; j < 4; j++) s[i][j] = 0.0f;

#pragma unroll
        for (int d = 0; d < HDIM; d += 4) {
            float4 q4[4], k4[4];
#pragma unroll
            for (int i = 0; i < 4; i++) q4[i] = *(const float4*)&Qs[4 * ty + i][d];
#pragma unroll
            for (int j = 0; j < 4; j++) k4[j] = *(const float4*)&Ks[4 * tx + j][d];
#pragma unroll
            for (int i = 0; i < 4; i++)
#pragma unroll
                for (int j = 0; j < 4; j++) {
                    s[i][j] = fmaf(q4[i].x, k4[j].x, s[i][j]);
                    s[i][j] = fmaf(q4[i].y, k4[j].y, s[i][j]);
                    s[i][j] = fmaf(q4[i].z, k4[j].z, s[i][j]);
                    s[i][j] = fmaf(q4[i].w, k4[j].w, s[i][j]);
                }
        }

#pragma unroll
        for (int i = 0; i < 4; i++) {
            float mx = -1e30f;
#pragma unroll
            for (int j = 0; j < 4; j++) {
                s[i][j] *= scale;
                mx = fmaxf(mx, s[i][j]);
            }
#pragma unroll
            for (int off = 1; off < 16; off <<= 1)
                mx = fmaxf(mx, __shfl_xor_sync(0xffffffffu, mx, off));

            const float mnew = fmaxf(m_i[i], mx);
            const float corr = __expf(m_i[i] - mnew);
            float rs = 0.0f;
#pragma unroll
            for (int j = 0; j < 4; j++) {
                const float p = __expf(s[i][j] - mnew);
                Ps[4 * ty + i][4 * tx + j] = p;
                rs += p;
            }
#pragma unroll
            for (int off = 1; off < 16; off <<= 1)
                rs += __shfl_xor_sync(0xffffffffu, rs, off);

            l_i[i] = l_i[i] * corr + rs;
            m_i[i] = mnew;
#pragma unroll
            for (int j = 0; j < 4; j++) O[i][j] *= corr;
        }
        __syncthreads();

#pragma unroll 4
        for (int kk = 0; kk < BKV; kk += 4) {
            float4 p4[4];
#pragma unroll
            for (int i = 0; i < 4; i++) p4[i] = *(const float4*)&Ps[4 * ty + i][kk];
            float4 v4[4];
#pragma unroll
            for (int t = 0; t < 4; t++) v4[t] = *(const float4*)&Vs[kk + t][4 * tx];
#pragma unroll
            for (int i = 0; i < 4; i++) {
                O[i][0] = fmaf(p4[i].x, v4[0].x, O[i][0]);
                O[i][1] = fmaf(p4[i].x, v4[0].y, O[i][1]);
                O[i][2] = fmaf(p4[i].x, v4[0].z, O[i][2]);
                O[i][3] = fmaf(p4[i].x, v4[0].w, O[i][3]);
                O[i][0] = fmaf(p4[i].y, v4[1].x, O[i][0]);
                O[i][1] = fmaf(p4[i].y, v4[1].y, O[i][1]);
                O[i][2] = fmaf(p4[i].y, v4[1].z, O[i][2]);
                O[i][3] = fmaf(p4[i].y, v4[1].w, O[i][3]);
                O[i][0] = fmaf(p4[i].z, v4[2].x, O[i][0]);
                O[i][1] = fmaf(p4[i].z, v4[2].y, O[i][1]);
                O[i][2] = fmaf(p4[i].z, v4[2].z, O[i][2]);
                O[i][3] = fmaf(p4[i].z, v4[2].w, O[i][3]);
                O[i][0] = fmaf(p4[i].w, v4[3].x, O[i][0]);
                O[i][1] = fmaf(p4[i].w, v4[3].y, O[i][1]);
                O[i][2] = fmaf(p4[i].w, v4[3].z, O[i][2]);
                O[i][3] = fmaf(p4[i].w, v4[3].w, O[i][3]);
            }
        }
        __syncthreads();
    }

#pragma unroll
    for (int i = 0; i < 4; i++) {
        const float inv = 1.0f / l_i[i];
        const int row = q0 + 4 * ty + i;
        float4 o4;
        o4.x = O[i][0] * inv;
        o4.y = O[i][1] * inv;
        o4.z = O[i][2] * inv;
        o4.w = O[i][3] * inv;
        *(float4*)(out + ((size_t)b * SEQ + row) * EMB + h * HDIM + 4 * tx) = o4;
    }
}

// ---------------- launcher ---------------------------------------------------
extern "C" void kernel_launch(void* const* d_in, const int* in_sizes, int n_in,
                              void* d_out, int out_size)
{
    const float* q  = (const float*)d_in[0];
    const float* k  = (const float*)d_in[1];
    const float* v  = (const float*)d_in[2];
    const float* Wq = (const float*)d_in[3];
    const float* bq = (const float*)d_in[4];
    const float* Wk = (const float*)d_in[5];
    const float* bk = (const float*)d_in[6];
    const float* Wv = (const float*)d_in[7];
    const float* bv = (const float*)d_in[8];
    const float* Wo = (const float*)d_in[9];
    const float* bo = (const float*)d_in[10];
    float* out = (float*)d_out;

    float *qp, *kp, *vp, *att;
    cudaGetSymbolAddress((void**)&qp,  g_qp);
    cudaGetSymbolAddress((void**)&kp,  g_kp);
    cudaGetSymbolAddress((void**)&vp,  g_vp);
    cudaGetSymbolAddress((void**)&att, g_att);

    cudaFuncSetAttribute(flash_attn_kernel,
                         cudaFuncAttributeMaxDynamicSharedMemorySize, SMEM_BYTES);

    dim3 gemm_grid(EMB / GBN, MROWS / GBM);  // (8, 64)
    gemm_bf16x3_kernel<<<gemm_grid, 256>>>(q, Wq, bq, qp);
    gemm_bf16x3_kernel<<<gemm_grid, 256>>>(k, Wk, bk, kp);
    gemm_bf16x3_kernel<<<gemm_grid, 256>>>(v, Wv, bv, vp);

    dim3 attn_grid(SEQ / BQ, BATCH * NHEAD); // (32, 64)
    flash_attn_kernel<<<attn_grid, 256, SMEM_BYTES>>>(qp, kp, vp, att);

    gemm_bf16x3_kernel<<<gemm_grid, 256>>>(att, Wo, bo, out);
}

// round 6
// speedup vs baseline: 2.2315x; 2.0977x over previous
#include <cuda_runtime.h>
#include <cuda_bf16.h>
#include <cstdint>

// Problem constants
#define BATCH 4
#define SEQ   2048
#define EMB   1024          // E == D
#define NHEAD 16
#define HDIM  64
#define MROWS (BATCH * SEQ) // 8192

// ---------------- scratch (static device globals; no allocation) ------------
__device__ float g_qp[MROWS * EMB];
__device__ float g_kp[MROWS * EMB];
__device__ float g_vp[MROWS * EMB];
__device__ float g_att[MROWS * EMB];

// ---------------- common mma helpers ----------------------------------------
__device__ __forceinline__ void mma_bf16(float& d0, float& d1, float& d2, float& d3,
                                         uint32_t a0, uint32_t a1, uint32_t a2, uint32_t a3,
                                         uint32_t b0, uint32_t b1)
{
    asm volatile(
        "mma.sync.aligned.m16n8k16.row.col.f32.bf16.bf16.f32 "
        "{%0,%1,%2,%3}, {%4,%5,%6,%7}, {%8,%9}, {%0,%1,%2,%3};\n"
        : "+f"(d0), "+f"(d1), "+f"(d2), "+f"(d3)
        : "r"(a0), "r"(a1), "r"(a2), "r"(a3), "r"(b0), "r"(b1));
}

__device__ __forceinline__ void split_bf16(float a, __nv_bfloat16& hi, __nv_bfloat16& lo)
{
    hi = __float2bfloat16(a);
    lo = __float2bfloat16(a - __bfloat162float(hi));
}

__device__ __forceinline__ uint32_t pack_bf16(float x, float y)
{
    __nv_bfloat162 t;
    t.x = __float2bfloat16(x);
    t.y = __float2bfloat16(y);
    return *(uint32_t*)&t;
}

__device__ __forceinline__ uint32_t pack_bf16_lo(float x, float y, uint32_t hi)
{
    __nv_bfloat162 h = *(__nv_bfloat162*)&hi;
    __nv_bfloat162 t;
    t.x = __float2bfloat16(x - __bfloat162float(h.x));
    t.y = __float2bfloat16(y - __bfloat162float(h.y));
    return *(uint32_t*)&t;
}

// ============================================================================
// Tensor-core GEMM: C = A @ W + bias, bf16x3 split.
// ============================================================================
#define GBM 128
#define GBN 128
#define GBK 32
#define KPAD 40

__global__ __launch_bounds__(256)
void gemm_bf16x3_kernel(const float* __restrict__ A,
                        const float* __restrict__ W,
                        const float* __restrict__ bias,
                        float* __restrict__ C)
{
    const int K  = EMB;
    const int Nc = EMB;

    __shared__ __nv_bfloat16 Ash[GBM][KPAD];
    __shared__ __nv_bfloat16 Asl[GBM][KPAD];
    __shared__ __nv_bfloat16 Bsh[GBN][KPAD];
    __shared__ __nv_bfloat16 Bsl[GBN][KPAD];

    const int tid  = threadIdx.x;
    const int warp = tid >> 5;
    const int lane = tid & 31;
    const int bx   = blockIdx.x;
    const int by   = blockIdx.y;

    const int wm = warp >> 2;
    const int wn = warp & 3;
    const int grp = lane >> 2;
    const int kp  = lane & 3;

    const float* Aptr = A + (size_t)by * GBM * K;

    const int aRow  = tid >> 1;
    const int aKoff = (tid & 1) * 16;
    const int bK    = tid >> 3;
    const int bNoff = (tid & 7) * 16;

    float acc[4][4][4];
#pragma unroll
    for (int i = 0; i < 4; i++)
#pragma unroll
        for (int j = 0; j < 4; j++)
#pragma unroll
            for (int c = 0; c < 4; c++) acc[i][j][c] = 0.0f;

    for (int k0 = 0; k0 < K; k0 += GBK) {
#pragma unroll
        for (int i = 0; i < 4; i++) {
            float4 a4 = *(const float4*)(Aptr + (size_t)aRow * K + k0 + aKoff + 4 * i);
            __nv_bfloat16 h, l;
            split_bf16(a4.x, h, l); Ash[aRow][aKoff + 4*i + 0] = h; Asl[aRow][aKoff + 4*i + 0] = l;
            split_bf16(a4.y, h, l); Ash[aRow][aKoff + 4*i + 1] = h; Asl[aRow][aKoff + 4*i + 1] = l;
            split_bf16(a4.z, h, l); Ash[aRow][aKoff + 4*i + 2] = h; Asl[aRow][aKoff + 4*i + 2] = l;
            split_bf16(a4.w, h, l); Ash[aRow][aKoff + 4*i + 3] = h; Asl[aRow][aKoff + 4*i + 3] = l;
        }
#pragma unroll
        for (int i = 0; i < 4; i++) {
            float4 b4 = *(const float4*)(W + (size_t)(k0 + bK) * Nc + bx * GBN + bNoff + 4 * i);
            __nv_bfloat16 h, l;
            split_bf16(b4.x, h, l); Bsh[bNoff + 4*i + 0][bK] = h; Bsl[bNoff + 4*i + 0][bK] = l;
            split_bf16(b4.y, h, l); Bsh[bNoff + 4*i + 1][bK] = h; Bsl[bNoff + 4*i + 1][bK] = l;
            split_bf16(b4.z, h, l); Bsh[bNoff + 4*i + 2][bK] = h; Bsl[bNoff + 4*i + 2][bK] = l;
            split_bf16(b4.w, h, l); Bsh[bNoff + 4*i + 3][bK] = h; Bsl[bNoff + 4*i + 3][bK] = l;
        }
        __syncthreads();

#pragma unroll
        for (int ks = 0; ks < GBK; ks += 16) {
            uint32_t bh[4][2], bl[4][2];
#pragma unroll
            for (int ni = 0; ni < 4; ni++) {
                const int n = wn * 32 + ni * 8 + grp;
                bh[ni][0] = *(const uint32_t*)&Bsh[n][ks + kp * 2];
                bh[ni][1] = *(const uint32_t*)&Bsh[n][ks + kp * 2 + 8];
                bl[ni][0] = *(const uint32_t*)&Bsl[n][ks + kp * 2];
                bl[ni][1] = *(const uint32_t*)&Bsl[n][ks + kp * 2 + 8];
            }
#pragma unroll
            for (int mi = 0; mi < 4; mi++) {
                const int r = wm * 64 + mi * 16 + grp;
                uint32_t ah0 = *(const uint32_t*)&Ash[r    ][ks + kp * 2];
                uint32_t ah1 = *(const uint32_t*)&Ash[r + 8][ks + kp * 2];
                uint32_t ah2 = *(const uint32_t*)&Ash[r    ][ks + kp * 2 + 8];
                uint32_t ah3 = *(const uint32_t*)&Ash[r + 8][ks + kp * 2 + 8];
                uint32_t al0 = *(const uint32_t*)&Asl[r    ][ks + kp * 2];
                uint32_t al1 = *(const uint32_t*)&Asl[r + 8][ks + kp * 2];
                uint32_t al2 = *(const uint32_t*)&Asl[r    ][ks + kp * 2 + 8];
                uint32_t al3 = *(const uint32_t*)&Asl[r + 8][ks + kp * 2 + 8];
#pragma unroll
                for (int ni = 0; ni < 4; ni++) {
                    float* d = acc[mi][ni];
                    mma_bf16(d[0], d[1], d[2], d[3], ah0, ah1, ah2, ah3, bh[ni][0], bh[ni][1]);
                    mma_bf16(d[0], d[1], d[2], d[3], ah0, ah1, ah2, ah3, bl[ni][0], bl[ni][1]);
                    mma_bf16(d[0], d[1], d[2], d[3], al0, al1, al2, al3, bh[ni][0], bh[ni][1]);
                }
            }
        }
        __syncthreads();
    }

#pragma unroll
    for (int mi = 0; mi < 4; mi++) {
        const int r = by * GBM + wm * 64 + mi * 16 + grp;
#pragma unroll
        for (int ni = 0; ni < 4; ni++) {
            const int c = bx * GBN + wn * 32 + ni * 8 + kp * 2;
            const float b0 = bias[c], b1 = bias[c + 1];
            float2 o0 = make_float2(acc[mi][ni][0] + b0, acc[mi][ni][1] + b1);
            float2 o1 = make_float2(acc[mi][ni][2] + b0, acc[mi][ni][3] + b1);
            *(float2*)(C + (size_t)r * Nc + c)       = o0;
            *(float2*)(C + (size_t)(r + 8) * Nc + c) = o1;
        }
    }
}

// ============================================================================
// Tensor-core flash attention (bf16x3, 4 warps, BQ=64, BKV=64)
// ============================================================================
#define BQ   64
#define BKV  64
#define KVPAD 72   // bf16 row stride: 144B -> conflict-free frag loads

__global__ __launch_bounds__(128)
void flash_attn_tc_kernel(const float* __restrict__ qp,
                          const float* __restrict__ kp,
                          const float* __restrict__ vp,
                          float* __restrict__ out)
{
    __shared__ __nv_bfloat16 Ksh[BKV][KVPAD];
    __shared__ __nv_bfloat16 Ksl[BKV][KVPAD];
    __shared__ __nv_bfloat16 Vsh[BKV][KVPAD];
    __shared__ __nv_bfloat16 Vsl[BKV][KVPAD];

    const int tid  = threadIdx.x;
    const int warp = tid >> 5;
    const int lane = tid & 31;
    const int grp  = lane >> 2;   // 0..7
    const int kq   = lane & 3;    // 0..3

    const int bh = blockIdx.y;
    const int b  = bh / NHEAD;
    const int h  = bh % NHEAD;
    const int q0 = blockIdx.x * BQ;

    const float scale = 0.125f; // 1/sqrt(64)

    const float* qbase = qp + ((size_t)b * SEQ) * EMB + h * HDIM;
    const float* kbase = kp + ((size_t)b * SEQ) * EMB + h * HDIM;
    const float* vbase = vp + ((size_t)b * SEQ) * EMB + h * HDIM;

    // ---- preload Q fragments (hi/lo) to registers: rows warp*16 + grp(+8) --
    uint32_t qh[4][4], ql[4][4];
    {
        const int r0 = q0 + warp * 16 + grp;
#pragma unroll
        for (int kc = 0; kc < 4; kc++) {
#pragma unroll
            for (int reg = 0; reg < 4; reg++) {
                const int row = r0 + (reg & 1) * 8;
                const int col = kc * 16 + (reg >> 1) * 8 + kq * 2;
                float2 v = *(const float2*)(qbase + (size_t)row * EMB + col);
                qh[kc][reg] = pack_bf16(v.x, v.y);
                ql[kc][reg] = pack_bf16_lo(v.x, v.y, qh[kc][reg]);
            }
        }
    }

    float o[8][4];
#pragma unroll
    for (int j = 0; j < 8; j++)
#pragma unroll
        for (int c = 0; c < 4; c++) o[j][c] = 0.0f;
    float m0 = -1e30f, m1 = -1e30f, l0 = 0.0f, l1 = 0.0f;

    for (int t0 = 0; t0 < SEQ; t0 += BKV) {
        // ---- cooperative load + split of K,V tiles (coalesced) ----
#pragma unroll
        for (int i = 0; i < 8; i++) {
            const int idx = tid + 128 * i;
            const int row = idx >> 4;
            const int c   = (idx & 15) * 4;
            float4 k4 = *(const float4*)(kbase + (size_t)(t0 + row) * EMB + c);
            float4 v4 = *(const float4*)(vbase + (size_t)(t0 + row) * EMB + c);
            __nv_bfloat16 hx, lx, hy, ly, hz, lz, hw, lw;
            split_bf16(k4.x, hx, lx); split_bf16(k4.y, hy, ly);
            split_bf16(k4.z, hz, lz); split_bf16(k4.w, hw, lw);
            *(__nv_bfloat162*)&Ksh[row][c]     = __nv_bfloat162(hx, hy);
            *(__nv_bfloat162*)&Ksh[row][c + 2] = __nv_bfloat162(hz, hw);
            *(__nv_bfloat162*)&Ksl[row][c]     = __nv_bfloat162(lx, ly);
            *(__nv_bfloat162*)&Ksl[row][c + 2] = __nv_bfloat162(lz, lw);
            split_bf16(v4.x, hx, lx); split_bf16(v4.y, hy, ly);
            split_bf16(v4.z, hz, lz); split_bf16(v4.w, hw, lw);
            *(__nv_bfloat162*)&Vsh[row][c]     = __nv_bfloat162(hx, hy);
            *(__nv_bfloat162*)&Vsh[row][c + 2] = __nv_bfloat162(hz, hw);
            *(__nv_bfloat162*)&Vsl[row][c]     = __nv_bfloat162(lx, ly);
            *(__nv_bfloat162*)&Vsl[row][c + 2] = __nv_bfloat162(lz, lw);
        }
        __syncthreads();

        // ---- S = Q K^T (bf16x3) ----
        float s[8][4];
#pragma unroll
        for (int j = 0; j < 8; j++)
#pragma unroll
            for (int c = 0; c < 4; c++) s[j][c] = 0.0f;

#pragma unroll
        for (int kc = 0; kc < 4; kc++) {
#pragma unroll
            for (int j = 0; j < 8; j++) {
                const int n = j * 8 + grp;
                uint32_t kb0h = *(const uint32_t*)&Ksh[n][kc * 16 + kq * 2];
                uint32_t kb1h = *(const uint32_t*)&Ksh[n][kc * 16 + kq * 2 + 8];
                uint32_t kb0l = *(const uint32_t*)&Ksl[n][kc * 16 + kq * 2];
                uint32_t kb1l = *(const uint32_t*)&Ksl[n][kc * 16 + kq * 2 + 8];
                mma_bf16(s[j][0], s[j][1], s[j][2], s[j][3],
                         qh[kc][0], qh[kc][1], qh[kc][2], qh[kc][3], kb0h, kb1h);
                mma_bf16(s[j][0], s[j][1], s[j][2], s[j][3],
                         qh[kc][0], qh[kc][1], qh[kc][2], qh[kc][3], kb0l, kb1l);
                mma_bf16(s[j][0], s[j][1], s[j][2], s[j][3],
                         ql[kc][0], ql[kc][1], ql[kc][2], ql[kc][3], kb0h, kb1h);
            }
        }

        // ---- online softmax (rows grp and grp+8) ----
        float mx0 = -1e30f, mx1 = -1e30f;
#pragma unroll
        for (int j = 0; j < 8; j++) {
            s[j][0] *= scale; s[j][1] *= scale; s[j][2] *= scale; s[j][3] *= scale;
            mx0 = fmaxf(mx0, fmaxf(s[j][0], s[j][1]));
            mx1 = fmaxf(mx1, fmaxf(s[j][2], s[j][3]));
        }
#pragma unroll
        for (int off = 1; off < 4; off <<= 1) {
            mx0 = fmaxf(mx0, __shfl_xor_sync(0xffffffffu, mx0, off));
            mx1 = fmaxf(mx1, __shfl_xor_sync(0xffffffffu, mx1, off));
        }
        const float mn0 = fmaxf(m0, mx0);
        const float mn1 = fmaxf(m1, mx1);
        const float corr0 = __expf(m0 - mn0);
        const float corr1 = __expf(m1 - mn1);
        float la0 = 0.0f, la1 = 0.0f;
#pragma unroll
        for (int j = 0; j < 8; j++) {
            s[j][0] = __expf(s[j][0] - mn0);
            s[j][1] = __expf(s[j][1] - mn0);
            s[j][2] = __expf(s[j][2] - mn1);
            s[j][3] = __expf(s[j][3] - mn1);
            la0 += s[j][0] + s[j][1];
            la1 += s[j][2] + s[j][3];
        }
#pragma unroll
        for (int off = 1; off < 4; off <<= 1) {
            la0 += __shfl_xor_sync(0xffffffffu, la0, off);
            la1 += __shfl_xor_sync(0xffffffffu, la1, off);
        }
        l0 = l0 * corr0 + la0;
        l1 = l1 * corr1 + la1;
        m0 = mn0; m1 = mn1;
#pragma unroll
        for (int j = 0; j < 8; j++) {
            o[j][0] *= corr0; o[j][1] *= corr0;
            o[j][2] *= corr1; o[j][3] *= corr1;
        }

        // ---- O += P V  (P from registers, V via ldmatrix.trans) ----
#pragma unroll
        for (int kc = 0; kc < 4; kc++) {
            uint32_t ph[4], pl[4];
            ph[0] = pack_bf16(s[2*kc][0],     s[2*kc][1]);
            ph[1] = pack_bf16(s[2*kc][2],     s[2*kc][3]);
            ph[2] = pack_bf16(s[2*kc + 1][0], s[2*kc + 1][1]);
            ph[3] = pack_bf16(s[2*kc + 1][2], s[2*kc + 1][3]);
            pl[0] = pack_bf16_lo(s[2*kc][0],     s[2*kc][1],     ph[0]);
            pl[1] = pack_bf16_lo(s[2*kc][2],     s[2*kc][3],     ph[1]);
            pl[2] = pack_bf16_lo(s[2*kc + 1][0], s[2*kc + 1][1], ph[2]);
            pl[3] = pack_bf16_lo(s[2*kc + 1][2], s[2*kc + 1][3], ph[3]);

#pragma unroll
            for (int j2 = 0; j2 < 4; j2++) {
                const int vrow = kc * 16 + (lane & 15);
                const int vcol = j2 * 16 + (lane >> 4) * 8;
                uint32_t vh[4], vl[4];
                uint32_t ah = (uint32_t)__cvta_generic_to_shared(&Vsh[vrow][vcol]);
                uint32_t al = (uint32_t)__cvta_generic_to_shared(&Vsl[vrow][vcol]);
                asm volatile("ldmatrix.sync.aligned.m8n8.x4.trans.shared.b16 "
                             "{%0,%1,%2,%3}, [%4];"
                             : "=r"(vh[0]), "=r"(vh[1]), "=r"(vh[2]), "=r"(vh[3]) : "r"(ah));
                asm volatile("ldmatrix.sync.aligned.m8n8.x4.trans.shared.b16 "
                             "{%0,%1,%2,%3}, [%4];"
                             : "=r"(vl[0]), "=r"(vl[1]), "=r"(vl[2]), "=r"(vl[3]) : "r"(al));
                float* d0 = o[2 * j2];
                float* d1 = o[2 * j2 + 1];
                mma_bf16(d0[0], d0[1], d0[2], d0[3], ph[0], ph[1], ph[2], ph[3], vh[0], vh[1]);
                mma_bf16(d0[0], d0[1], d0[2], d0[3], ph[0], ph[1], ph[2], ph[3], vl[0], vl[1]);
                mma_bf16(d0[0], d0[1], d0[2], d0[3], pl[0], pl[1], pl[2], pl[3], vh[0], vh[1]);
                mma_bf16(d1[0], d1[1], d1[2], d1[3], ph[0], ph[1], ph[2], ph[3], vh[2], vh[3]);
                mma_bf16(d1[0], d1[1], d1[2], d1[3], ph[0], ph[1], ph[2], ph[3], vl[2], vl[3]);
                mma_bf16(d1[0], d1[1], d1[2], d1[3], pl[0], pl[1], pl[2], pl[3], vh[2], vh[3]);
            }
        }
        __syncthreads();
    }

    // ---- epilogue: normalize + write [b, n, h*64 + d] ----
    const float inv0 = 1.0f / l0;
    const float inv1 = 1.0f / l1;
    const int r0 = q0 + warp * 16 + grp;
#pragma unroll
    for (int j = 0; j < 8; j++) {
        const int col = h * HDIM + j * 8 + kq * 2;
        *(float2*)(out + ((size_t)b * SEQ + r0) * EMB + col) =
            make_float2(o[j][0] * inv0, o[j][1] * inv0);
        *(float2*)(out + ((size_t)b * SEQ + r0 + 8) * EMB + col) =
            make_float2(o[j][2] * inv1, o[j][3] * inv1);
    }
}

// ---------------- launcher ---------------------------------------------------
extern "C" void kernel_launch(void* const* d_in, const int* in_sizes, int n_in,
                              void* d_out, int out_size)
{
    const float* q  = (const float*)d_in[0];
    const float* k  = (const float*)d_in[1];
    const float* v  = (const float*)d_in[2];
    const float* Wq = (const float*)d_in[3];
    const float* bq = (const float*)d_in[4];
    const float* Wk = (const float*)d_in[5];
    const float* bk = (const float*)d_in[6];
    const float* Wv = (const float*)d_in[7];
    const float* bv = (const float*)d_in[8];
    const float* Wo = (const float*)d_in[9];
    const float* bo = (const float*)d_in[10];
    float* out = (float*)d_out;

    float *qp, *kp, *vp, *att;
    cudaGetSymbolAddress((void**)&qp,  g_qp);
    cudaGetSymbolAddress((void**)&kp,  g_kp);
    cudaGetSymbolAddress((void**)&vp,  g_vp);
    cudaGetSymbolAddress((void**)&att, g_att);

    dim3 gemm_grid(EMB / GBN, MROWS / GBM);  // (8, 64)
    gemm_bf16x3_kernel<<<gemm_grid, 256>>>(q, Wq, bq, qp);
    gemm_bf16x3_kernel<<<gemm_grid, 256>>>(k, Wk, bk, kp);
    gemm_bf16x3_kernel<<<gemm_grid, 256>>>(v, Wv, bv, vp);

    dim3 attn_grid(SEQ / BQ, BATCH * NHEAD); // (32, 64)
    flash_attn_tc_kernel<<<attn_grid, 128>>>(qp, kp, vp, att);

    gemm_bf16x3_kernel<<<gemm_grid, 256>>>(att, Wo, bo, out);
}

// round 8
// speedup vs baseline: 3.4399x; 1.5415x over previous
#include <cuda_runtime.h>
#include <cuda_bf16.h>
#include <cstdint>

// Problem constants
#define BATCH 4
#define SEQ   2048
#define EMB   1024          // E == D
#define NHEAD 16
#define HDIM  64
#define MROWS (BATCH * SEQ) // 8192

// ---------------- scratch (static device globals; no allocation) ------------
__device__ __nv_bfloat16 g_inh[MROWS * EMB];
__device__ __nv_bfloat16 g_inl[MROWS * EMB];
__device__ __nv_bfloat16 g_qph[MROWS * EMB];
__device__ __nv_bfloat16 g_qpl[MROWS * EMB];
__device__ __nv_bfloat16 g_kph[MROWS * EMB];
__device__ __nv_bfloat16 g_kpl[MROWS * EMB];
__device__ __nv_bfloat16 g_vph[MROWS * EMB];
__device__ __nv_bfloat16 g_vpl[MROWS * EMB];
__device__ __nv_bfloat16 g_atth[MROWS * EMB];
__device__ __nv_bfloat16 g_attl[MROWS * EMB];
__device__ __nv_bfloat16 g_wth[4][EMB * EMB];  // transposed [N][K] hi
__device__ __nv_bfloat16 g_wtl[4][EMB * EMB];  // transposed [N][K] lo

// ---------------- helpers ----------------------------------------------------
__device__ __forceinline__ void mma_bf16(float& d0, float& d1, float& d2, float& d3,
                                         uint32_t a0, uint32_t a1, uint32_t a2, uint32_t a3,
                                         uint32_t b0, uint32_t b1)
{
    asm volatile(
        "mma.sync.aligned.m16n8k16.row.col.f32.bf16.bf16.f32 "
        "{%0,%1,%2,%3}, {%4,%5,%6,%7}, {%8,%9}, {%0,%1,%2,%3};\n"
        : "+f"(d0), "+f"(d1), "+f"(d2), "+f"(d3)
        : "r"(a0), "r"(a1), "r"(a2), "r"(a3), "r"(b0), "r"(b1));
}

__device__ __forceinline__ void split_bf16(float a, __nv_bfloat16& hi, __nv_bfloat16& lo)
{
    hi = __float2bfloat16(a);
    lo = __float2bfloat16(a - __bfloat162float(hi));
}

__device__ __forceinline__ uint32_t pack_bf16(float x, float y)
{
    __nv_bfloat162 t;
    t.x = __float2bfloat16(x);
    t.y = __float2bfloat16(y);
    return *(uint32_t*)&t;
}

__device__ __forceinline__ uint32_t pack_bf16_lo(float x, float y, uint32_t hi)
{
    __nv_bfloat162 h = *(__nv_bfloat162*)&hi;
    __nv_bfloat162 t;
    t.x = __float2bfloat16(x - __bfloat162float(h.x));
    t.y = __float2bfloat16(y - __bfloat162float(h.y));
    return *(uint32_t*)&t;
}

__device__ __forceinline__ uint32_t smaddr(const void* p)
{
    return (uint32_t)__cvta_generic_to_shared(p);
}

__device__ __forceinline__ void ldsm_x4(uint32_t& r0, uint32_t& r1, uint32_t& r2, uint32_t& r3,
                                        uint32_t addr)
{
    asm volatile("ldmatrix.sync.aligned.m8n8.x4.shared.b16 {%0,%1,%2,%3}, [%4];"
                 : "=r"(r0), "=r"(r1), "=r"(r2), "=r"(r3) : "r"(addr));
}

// ============================================================================
// Pre-pass 1: split fp32 activation -> hi/lo bf16 (same layout)
// ============================================================================
__global__ __launch_bounds__(256)
void split_kernel(const float* __restrict__ X,
                  __nv_bfloat16* __restrict__ Xh,
                  __nv_bfloat16* __restrict__ Xl)
{
    const int i = (blockIdx.x * 256 + threadIdx.x) * 4;
    float4 v = *(const float4*)(X + i);
    __nv_bfloat16 h0, l0, h1, l1, h2, l2, h3, l3;
    split_bf16(v.x, h0, l0); split_bf16(v.y, h1, l1);
    split_bf16(v.z, h2, l2); split_bf16(v.w, h3, l3);
    *(__nv_bfloat162*)(Xh + i)     = __nv_bfloat162(h0, h1);
    *(__nv_bfloat162*)(Xh + i + 2) = __nv_bfloat162(h2, h3);
    *(__nv_bfloat162*)(Xl + i)     = __nv_bfloat162(l0, l1);
    *(__nv_bfloat162*)(Xl + i + 2) = __nv_bfloat162(l2, l3);
}

// ============================================================================
// Pre-pass 2: weight W[K][N] fp32 -> Wt hi/lo bf16 [N][K] (transposed)
// ============================================================================
__global__ __launch_bounds__(256)
void wsplit_kernel(const float* __restrict__ W,
                   __nv_bfloat16* __restrict__ Wth,
                   __nv_bfloat16* __restrict__ Wtl)
{
    __shared__ float tile[32][33];
    const int n0 = blockIdx.x * 32;
    const int k0 = blockIdx.y * 32;
    const int tx = threadIdx.x;     // 0..31
    const int ty = threadIdx.y;     // 0..7
#pragma unroll
    for (int j = 0; j < 4; j++)
        tile[ty + 8 * j][tx] = W[(size_t)(k0 + ty + 8 * j) * EMB + n0 + tx];
    __syncthreads();
#pragma unroll
    for (int j = 0; j < 4; j++) {
        float v = tile[tx][ty + 8 * j];
        __nv_bfloat16 h, l;
        split_bf16(v, h, l);
        Wth[(size_t)(n0 + ty + 8 * j) * EMB + k0 + tx] = h;
        Wtl[(size_t)(n0 + ty + 8 * j) * EMB + k0 + tx] = l;
    }
}

// ============================================================================
// Tensor-core GEMM: C[M,N] = A[M,K] @ Wt[N,K]^T + bias  (bf16x3, ldmatrix)
// A hi/lo [M][K], B hi/lo [N][K]. BM=BN=128, BK=32, 256 threads.
// SPLIT_OUT: write hi/lo bf16; else fp32.
// ============================================================================
#define KPAD2 56   // bf16 row stride: 112B = 16B-aligned, conflict-free ldmatrix

template<bool SPLIT_OUT>
__global__ __launch_bounds__(256, 2)
void gemm_hl_kernel(const __nv_bfloat16* __restrict__ Ah,
                    const __nv_bfloat16* __restrict__ Al,
                    const __nv_bfloat16* __restrict__ Bth,
                    const __nv_bfloat16* __restrict__ Btl,
                    const float* __restrict__ bias,
                    float* __restrict__ Cf,
                    __nv_bfloat16* __restrict__ Ch,
                    __nv_bfloat16* __restrict__ Cl)
{
    extern __shared__ __nv_bfloat16 sm2[];
    __nv_bfloat16* As_h = sm2;
    __nv_bfloat16* As_l = sm2 + 128 * KPAD2;
    __nv_bfloat16* Bs_h = sm2 + 2 * 128 * KPAD2;
    __nv_bfloat16* Bs_l = sm2 + 3 * 128 * KPAD2;

    const int tid  = threadIdx.x;
    const int warp = tid >> 5;
    const int lane = tid & 31;
    const int wm   = warp >> 2;   // 0..1
    const int wn   = warp & 3;    // 0..3

    const int ldRow = tid >> 1;          // 0..127
    const int ldK   = (tid & 1) * 16;    // 0 or 16

    const __nv_bfloat16* Ah_p = Ah  + (size_t)(blockIdx.y * 128 + ldRow) * EMB + ldK;
    const __nv_bfloat16* Al_p = Al  + (size_t)(blockIdx.y * 128 + ldRow) * EMB + ldK;
    const __nv_bfloat16* Bh_p = Bth + (size_t)(blockIdx.x * 128 + ldRow) * EMB + ldK;
    const __nv_bfloat16* Bl_p = Btl + (size_t)(blockIdx.x * 128 + ldRow) * EMB + ldK;

    float acc[4][4][4];
#pragma unroll
    for (int i = 0; i < 4; i++)
#pragma unroll
        for (int j = 0; j < 4; j++)
#pragma unroll
            for (int c = 0; c < 4; c++) acc[i][j][c] = 0.0f;

    const int smBase = ldRow * KPAD2 + ldK;

    for (int k0 = 0; k0 < EMB; k0 += 32) {
        *(uint4*)&As_h[smBase]     = *(const uint4*)(Ah_p + k0);
        *(uint4*)&As_h[smBase + 8] = *(const uint4*)(Ah_p + k0 + 8);
        *(uint4*)&As_l[smBase]     = *(const uint4*)(Al_p + k0);
        *(uint4*)&As_l[smBase + 8] = *(const uint4*)(Al_p + k0 + 8);
        *(uint4*)&Bs_h[smBase]     = *(const uint4*)(Bh_p + k0);
        *(uint4*)&Bs_h[smBase + 8] = *(const uint4*)(Bh_p + k0 + 8);
        *(uint4*)&Bs_l[smBase]     = *(const uint4*)(Bl_p + k0);
        *(uint4*)&Bs_l[smBase + 8] = *(const uint4*)(Bl_p + k0 + 8);
        __syncthreads();

#pragma unroll
        for (int ks = 0; ks < 32; ks += 16) {
            // B fragments: 2x ldmatrix.x4 per hi/lo cover 32 n
            uint32_t bh[4][2], bl[4][2];
#pragma unroll
            for (int p = 0; p < 2; p++) {
                const int n0  = wn * 32 + p * 16;
                const int row = n0 + (lane & 7) + ((lane >> 4) & 1) * 8;
                const int kc  = ks + ((lane >> 3) & 1) * 8;
                uint32_t ad = smaddr(&Bs_h[row * KPAD2 + kc]);
                ldsm_x4(bh[2*p][0], bh[2*p][1], bh[2*p+1][0], bh[2*p+1][1], ad);
                ad = smaddr(&Bs_l[row * KPAD2 + kc]);
                ldsm_x4(bl[2*p][0], bl[2*p][1], bl[2*p+1][0], bl[2*p+1][1], ad);
            }
#pragma unroll
            for (int mi = 0; mi < 4; mi++) {
                const int r  = wm * 64 + mi * 16 + (lane & 15);
                const int kc = ks + ((lane >> 4) & 1) * 8;
                uint32_t ah0, ah1, ah2, ah3, al0, al1, al2, al3;
                ldsm_x4(ah0, ah1, ah2, ah3, smaddr(&As_h[r * KPAD2 + kc]));
                ldsm_x4(al0, al1, al2, al3, smaddr(&As_l[r * KPAD2 + kc]));
#pragma unroll
                for (int ni = 0; ni < 4; ni++) {
                    float* d = acc[mi][ni];
                    mma_bf16(d[0], d[1], d[2], d[3], ah0, ah1, ah2, ah3, bh[ni][0], bh[ni][1]);
                    mma_bf16(d[0], d[1], d[2], d[3], ah0, ah1, ah2, ah3, bl[ni][0], bl[ni][1]);
                    mma_bf16(d[0], d[1], d[2], d[3], al0, al1, al2, al3, bh[ni][0], bh[ni][1]);
                }
            }
        }
        __syncthreads();
    }

    // epilogue
    const int grp = lane >> 2;
    const int kp  = lane & 3;
#pragma unroll
    for (int mi = 0; mi < 4; mi++) {
        const int r = blockIdx.y * 128 + wm * 64 + mi * 16 + grp;
#pragma unroll
        for (int ni = 0; ni < 4; ni++) {
            const int c = blockIdx.x * 128 + wn * 32 + ni * 8 + kp * 2;
            const float b0 = bias[c], b1 = bias[c + 1];
            const float x0 = acc[mi][ni][0] + b0, x1 = acc[mi][ni][1] + b1;
            const float x2 = acc[mi][ni][2] + b0, x3 = acc[mi][ni][3] + b1;
            if (SPLIT_OUT) {
                uint32_t h0 = pack_bf16(x0, x1);
                uint32_t l0 = pack_bf16_lo(x0, x1, h0);
                uint32_t h1 = pack_bf16(x2, x3);
                uint32_t l1 = pack_bf16_lo(x2, x3, h1);
                *(uint32_t*)(Ch + (size_t)r * EMB + c)       = h0;
                *(uint32_t*)(Cl + (size_t)r * EMB + c)       = l0;
                *(uint32_t*)(Ch + (size_t)(r + 8) * EMB + c) = h1;
                *(uint32_t*)(Cl + (size_t)(r + 8) * EMB + c) = l1;
            } else {
                *(float2*)(Cf + (size_t)r * EMB + c)       = make_float2(x0, x1);
                *(float2*)(Cf + (size_t)(r + 8) * EMB + c) = make_float2(x2, x3);
            }
        }
    }
}

// ============================================================================
// Tensor-core flash attention (bf16x3) — consumes prepacked hi/lo bf16
// ============================================================================
#define BQ   64
#define BKV  64
#define KVPAD 72   // bf16 row stride: 144B = 16B-aligned, conflict-free

__global__ __launch_bounds__(128)
void flash_attn_tc_kernel(const __nv_bfloat16* __restrict__ qh_g,
                          const __nv_bfloat16* __restrict__ ql_g,
                          const __nv_bfloat16* __restrict__ kh_g,
                          const __nv_bfloat16* __restrict__ kl_g,
                          const __nv_bfloat16* __restrict__ vh_g,
                          const __nv_bfloat16* __restrict__ vl_g,
                          __nv_bfloat16* __restrict__ atth,
                          __nv_bfloat16* __restrict__ attl)
{
    __shared__ __nv_bfloat16 Ksh[BKV][KVPAD];
    __shared__ __nv_bfloat16 Ksl[BKV][KVPAD];
    __shared__ __nv_bfloat16 Vsh[BKV][KVPAD];
    __shared__ __nv_bfloat16 Vsl[BKV][KVPAD];

    const int tid  = threadIdx.x;
    const int warp = tid >> 5;
    const int lane = tid & 31;
    const int grp  = lane >> 2;   // 0..7
    const int kq   = lane & 3;    // 0..3

    const int bh_i = blockIdx.y;
    const int b    = bh_i / NHEAD;
    const int h    = bh_i % NHEAD;
    const int q0   = blockIdx.x * BQ;

    const float scale = 0.125f; // 1/sqrt(64)

    const __nv_bfloat16* qh_b = qh_g + ((size_t)b * SEQ) * EMB + h * HDIM;
    const __nv_bfloat16* ql_b = ql_g + ((size_t)b * SEQ) * EMB + h * HDIM;
    const __nv_bfloat16* kh_b = kh_g + ((size_t)b * SEQ) * EMB + h * HDIM;
    const __nv_bfloat16* kl_b = kl_g + ((size_t)b * SEQ) * EMB + h * HDIM;
    const __nv_bfloat16* vh_b = vh_g + ((size_t)b * SEQ) * EMB + h * HDIM;
    const __nv_bfloat16* vl_b = vl_g + ((size_t)b * SEQ) * EMB + h * HDIM;

    // ---- preload Q fragments (prepacked hi/lo) ----
    uint32_t qh[4][4], ql[4][4];
    {
        const int r0 = q0 + warp * 16 + grp;
#pragma unroll
        for (int kc = 0; kc < 4; kc++) {
#pragma unroll
            for (int reg = 0; reg < 4; reg++) {
                const int row = r0 + (reg & 1) * 8;
                const int col = kc * 16 + (reg >> 1) * 8 + kq * 2;
                qh[kc][reg] = *(const uint32_t*)(qh_b + (size_t)row * EMB + col);
                ql[kc][reg] = *(const uint32_t*)(ql_b + (size_t)row * EMB + col);
            }
        }
    }

    float o[8][4];
#pragma unroll
    for (int j = 0; j < 8; j++)
#pragma unroll
        for (int c = 0; c < 4; c++) o[j][c] = 0.0f;
    float m0 = -1e30f, m1 = -1e30f, l0 = 0.0f, l1 = 0.0f;

    for (int t0 = 0; t0 < SEQ; t0 += BKV) {
        // ---- straight bf16 copies global -> smem ----
#pragma unroll
        for (int i = 0; i < 4; i++) {
            const int idx = tid + 128 * i;      // 0..511
            const int row = idx >> 3;
            const int ch  = (idx & 7) * 8;
            const size_t g = (size_t)(t0 + row) * EMB + ch;
            *(uint4*)&Ksh[row][ch] = *(const uint4*)(kh_b + g);
            *(uint4*)&Ksl[row][ch] = *(const uint4*)(kl_b + g);
            *(uint4*)&Vsh[row][ch] = *(const uint4*)(vh_b + g);
            *(uint4*)&Vsl[row][ch] = *(const uint4*)(vl_b + g);
        }
        __syncthreads();

        // ---- S = Q K^T (bf16x3) ----
        float s[8][4];
#pragma unroll
        for (int j = 0; j < 8; j++)
#pragma unroll
            for (int c = 0; c < 4; c++) s[j][c] = 0.0f;

#pragma unroll
        for (int kc = 0; kc < 4; kc++) {
#pragma unroll
            for (int j = 0; j < 8; j++) {
                const int n = j * 8 + grp;
                uint32_t kb0h = *(const uint32_t*)&Ksh[n][kc * 16 + kq * 2];
                uint32_t kb1h = *(const uint32_t*)&Ksh[n][kc * 16 + kq * 2 + 8];
                uint32_t kb0l = *(const uint32_t*)&Ksl[n][kc * 16 + kq * 2];
                uint32_t kb1l = *(const uint32_t*)&Ksl[n][kc * 16 + kq * 2 + 8];
                mma_bf16(s[j][0], s[j][1], s[j][2], s[j][3],
                         qh[kc][0], qh[kc][1], qh[kc][2], qh[kc][3], kb0h, kb1h);
                mma_bf16(s[j][0], s[j][1], s[j][2], s[j][3],
                         qh[kc][0], qh[kc][1], qh[kc][2], qh[kc][3], kb0l, kb1l);
                mma_bf16(s[j][0], s[j][1], s[j][2], s[j][3],
                         ql[kc][0], ql[kc][1], ql[kc][2], ql[kc][3], kb0h, kb1h);
            }
        }

        // ---- online softmax ----
        float mx0 = -1e30f, mx1 = -1e30f;
#pragma unroll
        for (int j = 0; j < 8; j++) {
            s[j][0] *= scale; s[j][1] *= scale; s[j][2] *= scale; s[j][3] *= scale;
            mx0 = fmaxf(mx0, fmaxf(s[j][0], s[j][1]));
            mx1 = fmaxf(mx1, fmaxf(s[j][2], s[j][3]));
        }
#pragma unroll
        for (int off = 1; off < 4; off <<= 1) {
            mx0 = fmaxf(mx0, __shfl_xor_sync(0xffffffffu, mx0, off));
            mx1 = fmaxf(mx1, __shfl_xor_sync(0xffffffffu, mx1, off));
        }
        const float mn0 = fmaxf(m0, mx0);
        const float mn1 = fmaxf(m1, mx1);
        const float corr0 = __expf(m0 - mn0);
        const float corr1 = __expf(m1 - mn1);
        float la0 = 0.0f, la1 = 0.0f;
#pragma unroll
        for (int j = 0; j < 8; j++) {
            s[j][0] = __expf(s[j][0] - mn0);
            s[j][1] = __expf(s[j][1] - mn0);
            s[j][2] = __expf(s[j][2] - mn1);
            s[j][3] = __expf(s[j][3] - mn1);
            la0 += s[j][0] + s[j][1];
            la1 += s[j][2] + s[j][3];
        }
#pragma unroll
        for (int off = 1; off < 4; off <<= 1) {
            la0 += __shfl_xor_sync(0xffffffffu, la0, off);
            la1 += __shfl_xor_sync(0xffffffffu, la1, off);
        }
        l0 = l0 * corr0 + la0;
        l1 = l1 * corr1 + la1;
        m0 = mn0; m1 = mn1;
#pragma unroll
        for (int j = 0; j < 8; j++) {
            o[j][0] *= corr0; o[j][1] *= corr0;
            o[j][2] *= corr1; o[j][3] *= corr1;
        }

        // ---- O += P V ----
#pragma unroll
        for (int kc = 0; kc < 4; kc++) {
            uint32_t ph[4], pl[4];
            ph[0] = pack_bf16(s[2*kc][0],     s[2*kc][1]);
            ph[1] = pack_bf16(s[2*kc][2],     s[2*kc][3]);
            ph[2] = pack_bf16(s[2*kc + 1][0], s[2*kc + 1][1]);
            ph[3] = pack_bf16(s[2*kc + 1][2], s[2*kc + 1][3]);
            pl[0] = pack_bf16_lo(s[2*kc][0],     s[2*kc][1],     ph[0]);
            pl[1] = pack_bf16_lo(s[2*kc][2],     s[2*kc][3],     ph[1]);
            pl[2] = pack_bf16_lo(s[2*kc + 1][0], s[2*kc + 1][1], ph[2]);
            pl[3] = pack_bf16_lo(s[2*kc + 1][2], s[2*kc + 1][3], ph[3]);

#pragma unroll
            for (int j2 = 0; j2 < 4; j2++) {
                const int vrow = kc * 16 + (lane & 15);
                const int vcol = j2 * 16 + (lane >> 4) * 8;
                uint32_t vh[4], vl[4];
                uint32_t ah = smaddr(&Vsh[vrow][vcol]);
                uint32_t al = smaddr(&Vsl[vrow][vcol]);
                asm volatile("ldmatrix.sync.aligned.m8n8.x4.trans.shared.b16 "
                             "{%0,%1,%2,%3}, [%4];"
                             : "=r"(vh[0]), "=r"(vh[1]), "=r"(vh[2]), "=r"(vh[3]) : "r"(ah));
                asm volatile("ldmatrix.sync.aligned.m8n8.x4.trans.shared.b16 "
                             "{%0,%1,%2,%3}, [%4];"
                             : "=r"(vl[0]), "=r"(vl[1]), "=r"(vl[2]), "=r"(vl[3]) : "r"(al));
                float* d0 = o[2 * j2];
                float* d1 = o[2 * j2 + 1];
                mma_bf16(d0[0], d0[1], d0[2], d0[3], ph[0], ph[1], ph[2], ph[3], vh[0], vh[1]);
                mma_bf16(d0[0], d0[1], d0[2], d0[3], ph[0], ph[1], ph[2], ph[3], vl[0], vl[1]);
                mma_bf16(d0[0], d0[1], d0[2], d0[3], pl[0], pl[1], pl[2], pl[3], vh[0], vh[1]);
                mma_bf16(d1[0], d1[1], d1[2], d1[3], ph[0], ph[1], ph[2], ph[3], vh[2], vh[3]);
                mma_bf16(d1[0], d1[1], d1[2], d1[3], ph[0], ph[1], ph[2], ph[3], vl[2], vl[3]);
                mma_bf16(d1[0], d1[1], d1[2], d1[3], pl[0], pl[1], pl[2], pl[3], vh[2], vh[3]);
            }
        }
        __syncthreads();
    }

    // ---- epilogue: normalize + write att hi/lo at [b, n, h*64 + d] ----
    const float inv0 = 1.0f / l0;
    const float inv1 = 1.0f / l1;
    const int r0 = q0 + warp * 16 + grp;
#pragma unroll
    for (int j = 0; j < 8; j++) {
        const int col = h * HDIM + j * 8 + kq * 2;
        const float a0 = o[j][0] * inv0, a1 = o[j][1] * inv0;
        const float a2 = o[j][2] * inv1, a3 = o[j][3] * inv1;
        uint32_t h0 = pack_bf16(a0, a1);
        uint32_t l0p = pack_bf16_lo(a0, a1, h0);
        uint32_t h1 = pack_bf16(a2, a3);
        uint32_t l1p = pack_bf16_lo(a2, a3, h1);
        *(uint32_t*)(atth + ((size_t)b * SEQ + r0) * EMB + col)     = h0;
        *(uint32_t*)(attl + ((size_t)b * SEQ + r0) * EMB + col)     = l0p;
        *(uint32_t*)(atth + ((size_t)b * SEQ + r0 + 8) * EMB + col) = h1;
        *(uint32_t*)(attl + ((size_t)b * SEQ + r0 + 8) * EMB + col) = l1p;
    }
}

// ---------------- launcher ---------------------------------------------------
#define GEMM_SMEM (4 * 128 * KPAD2 * 2)   // 57344 bytes

extern "C" void kernel_launch(void* const* d_in, const int* in_sizes, int n_in,
                              void* d_out, int out_size)
{
    const float* q  = (const float*)d_in[0];
    const float* k  = (const float*)d_in[1];
    const float* v  = (const float*)d_in[2];
    const float* Wq = (const float*)d_in[3];
    const float* bq = (const float*)d_in[4];
    const float* Wk = (const float*)d_in[5];
    const float* bk = (const float*)d_in[6];
    const float* Wv = (const float*)d_in[7];
    const float* bv = (const float*)d_in[8];
    const float* Wo = (const float*)d_in[9];
    const float* bo = (const float*)d_in[10];
    float* out = (float*)d_out;

    __nv_bfloat16 *inh, *inl, *qph, *qpl, *kph, *kpl, *vph, *vpl, *atth, *attl;
    __nv_bfloat16 *wth, *wtl;
    cudaGetSymbolAddress((void**)&inh,  g_inh);
    cudaGetSymbolAddress((void**)&inl,  g_inl);
    cudaGetSymbolAddress((void**)&qph,  g_qph);
    cudaGetSymbolAddress((void**)&qpl,  g_qpl);
    cudaGetSymbolAddress((void**)&kph,  g_kph);
    cudaGetSymbolAddress((void**)&kpl,  g_kpl);
    cudaGetSymbolAddress((void**)&vph,  g_vph);
    cudaGetSymbolAddress((void**)&vpl,  g_vpl);
    cudaGetSymbolAddress((void**)&atth, g_atth);
    cudaGetSymbolAddress((void**)&attl, g_attl);
    cudaGetSymbolAddress((void**)&wth,  g_wth);
    cudaGetSymbolAddress((void**)&wtl,  g_wtl);

    cudaFuncSetAttribute(gemm_hl_kernel<true>,
                         cudaFuncAttributeMaxDynamicSharedMemorySize, GEMM_SMEM);
    cudaFuncSetAttribute(gemm_hl_kernel<false>,
                         cudaFuncAttributeMaxDynamicSharedMemorySize, GEMM_SMEM);

    // weights: split + transpose
    dim3 wgrid(EMB / 32, EMB / 32);
    dim3 wblk(32, 8);
    const float* Ws[4] = {Wq, Wk, Wv, Wo};
    for (int i = 0; i < 4; i++)
        wsplit_kernel<<<wgrid, wblk>>>(Ws[i], wth + (size_t)i * EMB * EMB,
                                       wtl + (size_t)i * EMB * EMB);

    const int sblocks = (MROWS * EMB) / 4 / 256;
    dim3 ggrid(EMB / 128, MROWS / 128);  // (8, 64)

    split_kernel<<<sblocks, 256>>>(q, inh, inl);
    gemm_hl_kernel<true><<<ggrid, 256, GEMM_SMEM>>>(inh, inl, wth, wtl, bq,
                                                    nullptr, qph, qpl);
    split_kernel<<<sblocks, 256>>>(k, inh, inl);
    gemm_hl_kernel<true><<<ggrid, 256, GEMM_SMEM>>>(inh, inl,
                                                    wth + (size_t)1 * EMB * EMB,
                                                    wtl + (size_t)1 * EMB * EMB, bk,
                                                    nullptr, kph, kpl);
    split_kernel<<<sblocks, 256>>>(v, inh, inl);
    gemm_hl_kernel<true><<<ggrid, 256, GEMM_SMEM>>>(inh, inl,
                                                    wth + (size_t)2 * EMB * EMB,
                                                    wtl + (size_t)2 * EMB * EMB, bv,
                                                    nullptr, vph, vpl);

    dim3 attn_grid(SEQ / BQ, BATCH * NHEAD); // (32, 64)
    flash_attn_tc_kernel<<<attn_grid, 128>>>(qph, qpl, kph, kpl, vph, vpl, atth, attl);

    gemm_hl_kernel<false><<<ggrid, 256, GEMM_SMEM>>>(atth, attl,
                                                     wth + (size_t)3 * EMB * EMB,
                                                     wtl + (size_t)3 * EMB * EMB, bo,
                                                     out, nullptr, nullptr);
}